// round 11
// baseline (speedup 1.0000x reference)
#include <cuda_runtime.h>
#include <cuda_bf16.h>
#include <cuda_fp8.h>
#include <math_constants.h>
#include <cstdint>

#define D      768
#define BPREV  8192
#define BCUR   4096
#define KNB    5
#define KCB    8           // candidates kept per (row, j-block)
#define KC2    32          // global candidates rescored in fp32
#define JBLK   64          // number of 128-wide j blocks (8192/128)
#define CPR    (JBLK * KCB)   // 512 candidates per row
#define KCHUNK 64          // K elements (=bytes, fp8) per pipeline chunk
#define NCHUNK (D / KCHUNK)   // 12
#define STAGES 4
#define FP8_SCALE 16.0f    // power of 2; sims scale by 256 (order-preserving)

// smem layout (bytes): A/B tiles padded to 80B per 64B row
#define SA        80
#define TILE_BYTES (128 * SA)            // 10240 (one of A or B)
#define STAGE_BYTES (2 * TILE_BYTES)     // 20480 (A then B)
#define SIM_STRIDE 132                   // floats
#define SMEM_KNN  (STAGES * STAGE_BYTES) // 81920 >= Sim (67584)

// ---------------- device scratch ----------------
__device__ float   g_hp[BPREV * D];      // normalized previous (fp32)
__device__ uint8_t g_hp_f8[BPREV * D];   // normalized previous (e4m3, x16)
__device__ float   g_hc[BCUR * D];       // normalized current
__device__ float   g_sq[BCUR];
__device__ float g_cand_val[BCUR * CPR];
__device__ int   g_cand_idx[BCUR * CPR];
__device__ int   g_cand2[BCUR * KC2];
__device__ int   g_nbr[BCUR * KNB];

// ---------------- helpers ----------------
__device__ __forceinline__ uint32_t smem_to_u32(const void* p) {
    uint32_t a;
    asm("{ .reg .u64 t; cvta.to.shared.u64 t, %1; cvt.u32.u64 %0, t; }" : "=r"(a) : "l"(p));
    return a;
}
__device__ __forceinline__ bool better(float v1, int j1, float v2, int j2) {
    return (v1 > v2) || (v1 == v2 && j1 < j2);   // JAX top_k tie-break
}
template <int KK>
__device__ __forceinline__ void insertK(float v, int j, float* tv, int* tj) {
    if (!better(v, j, tv[KK - 1], tj[KK - 1])) return;
    tv[KK - 1] = v; tj[KK - 1] = j;
#pragma unroll
    for (int k = KK - 1; k > 0; --k) {
        if (better(tv[k], tj[k], tv[k - 1], tj[k - 1])) {
            float fv = tv[k]; tv[k] = tv[k - 1]; tv[k - 1] = fv;
            int   ij = tj[k]; tj[k] = tj[k - 1]; tj[k - 1] = ij;
        }
    }
}

// fp8 mma: D(16x8,f32) += A(16x32,e4m3 row) * B(8x32,e4m3 col)
__device__ __forceinline__ void mma_fp8(float* d, const uint32_t* a,
                                        const uint32_t* b, const float* c) {
    asm volatile(
        "mma.sync.aligned.m16n8k32.row.col.f32.e4m3.e4m3.f32 "
        "{%0,%1,%2,%3}, {%4,%5,%6,%7}, {%8,%9}, {%10,%11,%12,%13};\n"
        : "=f"(d[0]), "=f"(d[1]), "=f"(d[2]), "=f"(d[3])
        : "r"(a[0]), "r"(a[1]), "r"(a[2]), "r"(a[3]),
          "r"(b[0]), "r"(b[1]),
          "f"(c[0]), "f"(c[1]), "f"(c[2]), "f"(c[3]));
}
#define LDMATRIX_X4(r0, r1, r2, r3, addr) \
    asm volatile("ldmatrix.sync.aligned.m8n8.x4.shared.b16 {%0,%1,%2,%3}, [%4];" \
        : "=r"(r0), "=r"(r1), "=r"(r2), "=r"(r3) : "r"(addr))
#define CP_ASYNC_16(dst, src) \
    asm volatile("cp.async.cg.shared.global [%0], [%1], 16;" :: "r"(dst), "l"(src))
#define CP_ASYNC_COMMIT() asm volatile("cp.async.commit_group;")
#define CP_ASYNC_WAIT(n)  asm volatile("cp.async.wait_group %0;" :: "n"(n))

// ---------------- small kernels ----------------
__global__ void zero_out(float* out) { out[0] = 0.0f; }

// fused: blocks [0, BPREV) normalize previous -> g_hp + g_hp_f8 (x16)
//        blocks [BPREV, BPREV+BCUR) normalize current -> g_hc + g_sq
__global__ void normalize_all(const float* __restrict__ prev,
                              const float* __restrict__ cur) {
    const bool is_prev = blockIdx.x < BPREV;
    const int r = is_prev ? blockIdx.x : blockIdx.x - BPREV;
    const float* x = (is_prev ? prev : cur) + (size_t)r * D;
    __shared__ float red[256];
    float s = 0.f;
    for (int k = threadIdx.x; k < D; k += 256) { float v = x[k]; s += v * v; }
    red[threadIdx.x] = s;
    __syncthreads();
    for (int off = 128; off > 0; off >>= 1) {
        if (threadIdx.x < off) red[threadIdx.x] += red[threadIdx.x + off];
        __syncthreads();
    }
    float denom = fmaxf(sqrtf(red[0]), 1e-12f);
    float s2 = 0.f;
    for (int k = threadIdx.x; k < D; k += 256) {
        float v = x[k] / denom;
        if (is_prev) {
            g_hp[(size_t)r * D + k] = v;
            __nv_fp8_e4m3 f8(v * FP8_SCALE);
            g_hp_f8[(size_t)r * D + k] = *(uint8_t*)&f8;
        } else {
            g_hc[(size_t)r * D + k] = v;
            s2 += v * v;
        }
    }
    if (!is_prev) {
        __syncthreads();
        red[threadIdx.x] = s2;
        __syncthreads();
        for (int off = 128; off > 0; off >>= 1) {
            if (threadIdx.x < off) red[threadIdx.x] += red[threadIdx.x + off];
            __syncthreads();
        }
        if (threadIdx.x == 0) g_sq[r] = red[0];
    }
}

// ---------------- tensor-core kNN (fp8 mma.sync + ldmatrix + cp.async) -------
// grid (32, 64): 128 i-rows x 128 j-cols per CTA. 8 warps as 2(M) x 4(N).
__global__ void __launch_bounds__(256) knn_mma_kernel() {
    extern __shared__ char smem[];
    uint32_t smem_u32 = smem_to_u32(smem);
    const int tid    = threadIdx.x;
    const int wid    = tid >> 5;
    const int lane   = tid & 31;
    const int warp_m = wid >> 2;       // 0..1 -> rows warp_m*64
    const int warp_n = wid & 3;        // 0..3 -> cols warp_n*32
    const int i0 = blockIdx.x * 128;
    const int j0 = blockIdx.y * 128;

    float acc[4][4][4];
#pragma unroll
    for (int mf = 0; mf < 4; mf++)
#pragma unroll
        for (int nf = 0; nf < 4; nf++)
#pragma unroll
            for (int r = 0; r < 4; r++) acc[mf][nf][r] = 0.f;

    // staging: 64 B (=64 fp8 elems) per row per chunk; each thread 2x16B of A and B
    const int ld_row = tid >> 2;        // 0..63 (+64 for the second half)
    const int ld_c16 = tid & 3;
    const char* srcA0 = (const char*)&g_hp_f8[(size_t)(i0 + ld_row) * D + ld_c16 * 16];
    const char* srcA1 = (const char*)&g_hp_f8[(size_t)(i0 + 64 + ld_row) * D + ld_c16 * 16];
    const char* srcB0 = (const char*)&g_hp_f8[(size_t)(j0 + ld_row) * D + ld_c16 * 16];
    const char* srcB1 = (const char*)&g_hp_f8[(size_t)(j0 + 64 + ld_row) * D + ld_c16 * 16];
    const uint32_t dstA0 = smem_u32 + ld_row * SA + ld_c16 * 16;
    const uint32_t dstA1 = smem_u32 + (64 + ld_row) * SA + ld_c16 * 16;
    const uint32_t dstB0 = dstA0 + TILE_BYTES;
    const uint32_t dstB1 = dstA1 + TILE_BYTES;

    // ldmatrix lane-address components (fp8 16x32B tile == b16 16x16 tile)
    const int a_row_in  = (lane & 15);
    const int a_colbyte = (lane >> 4) * 16;
    const int b_row_in  = (lane & 7) + ((lane >> 4) << 3);
    const int b_colbyte = ((lane >> 3) & 1) * 16;
    const uint32_t aAddrBase = smem_u32 +
        (uint32_t)((warp_m * 64 + a_row_in) * SA + a_colbyte);
    const uint32_t bAddrBase = smem_u32 + TILE_BYTES +
        (uint32_t)((warp_n * 32 + b_row_in) * SA + b_colbyte);

    // prologue: issue first STAGES-1 chunks
#pragma unroll
    for (int s = 0; s < STAGES - 1; s++) {
        const uint32_t so = s * STAGE_BYTES;
        const size_t go = (size_t)s * KCHUNK;   // bytes (fp8 = 1B/elem)
        CP_ASYNC_16(dstA0 + so, srcA0 + go);
        CP_ASYNC_16(dstA1 + so, srcA1 + go);
        CP_ASYNC_16(dstB0 + so, srcB0 + go);
        CP_ASYNC_16(dstB1 + so, srcB1 + go);
        CP_ASYNC_COMMIT();
    }

    for (int c = 0; c < NCHUNK; c++) {
        CP_ASYNC_WAIT(STAGES - 2);
        __syncthreads();

        const uint32_t so = (uint32_t)(c & (STAGES - 1)) * STAGE_BYTES;
        uint32_t a[4][2][4];
        uint32_t b[2][4][2];
#pragma unroll
        for (int ks = 0; ks < 2; ks++) {        // ks = 32 fp8 elems = 32 B
#pragma unroll
            for (int mf = 0; mf < 4; mf++) {
                uint32_t addr = aAddrBase + so + (uint32_t)(mf * 16 * SA + ks * 32);
                LDMATRIX_X4(a[mf][ks][0], a[mf][ks][1], a[mf][ks][2], a[mf][ks][3], addr);
            }
#pragma unroll
            for (int nf2 = 0; nf2 < 2; nf2++) {
                uint32_t addr = bAddrBase + so + (uint32_t)(nf2 * 16 * SA + ks * 32);
                LDMATRIX_X4(b[ks][nf2 * 2][0], b[ks][nf2 * 2][1],
                            b[ks][nf2 * 2 + 1][0], b[ks][nf2 * 2 + 1][1], addr);
            }
        }
#pragma unroll
        for (int ks = 0; ks < 2; ks++)
#pragma unroll
            for (int mf = 0; mf < 4; mf++)
#pragma unroll
                for (int nf = 0; nf < 4; nf++)
                    mma_fp8(acc[mf][nf], a[mf][ks], b[ks][nf], acc[mf][nf]);

        // issue chunk c+STAGES-1 into the stage just freed
        const int cn = c + STAGES - 1;
        if (cn < NCHUNK) {
            const uint32_t sn = (uint32_t)(cn & (STAGES - 1)) * STAGE_BYTES;
            const size_t gn = (size_t)cn * KCHUNK;
            CP_ASYNC_16(dstA0 + sn, srcA0 + gn);
            CP_ASYNC_16(dstA1 + sn, srcA1 + gn);
            CP_ASYNC_16(dstB0 + sn, srcB0 + gn);
            CP_ASYNC_16(dstB1 + sn, srcB1 + gn);
        }
        CP_ASYNC_COMMIT();
    }
    CP_ASYNC_WAIT(0);
    __syncthreads();

    // stage sims to smem (scaled by 256 — order preserved; rescore is fp32)
    float* Sim = (float*)smem;
#pragma unroll
    for (int mf = 0; mf < 4; mf++) {
        int r0 = warp_m * 64 + mf * 16 + (lane >> 2);
#pragma unroll
        for (int nf = 0; nf < 4; nf++) {
            int c0 = warp_n * 32 + nf * 8 + (lane & 3) * 2;
            Sim[r0 * SIM_STRIDE + c0]           = acc[mf][nf][0];
            Sim[r0 * SIM_STRIDE + c0 + 1]       = acc[mf][nf][1];
            Sim[(r0 + 8) * SIM_STRIDE + c0]     = acc[mf][nf][2];
            Sim[(r0 + 8) * SIM_STRIDE + c0 + 1] = acc[mf][nf][3];
        }
    }
    __syncthreads();

    // scan: 2 threads per row, 64 cols each, keep top-8 per half
    const int row  = tid >> 1;
    const int half = tid & 1;
    const int ig   = i0 + row;
    float tv[KCB]; int tj[KCB];
#pragma unroll
    for (int k = 0; k < KCB; k++) { tv[k] = -CUDART_INF_F; tj[k] = 0x7fffffff; }
#pragma unroll 4
    for (int c0 = 0; c0 < 64; c0++) {
        int cc = half * 64 + c0;
        float v = Sim[row * SIM_STRIDE + cc];
        int jg = j0 + cc;
        if (jg != ig) insertK<KCB>(v, jg, tv, tj);
    }
    __syncthreads();
    // half 1 parks its list in smem scratch (Sim area is free now)
    float* scratch = (float*)smem;          // 128 rows x 16 slots
    if (half == 1) {
#pragma unroll
        for (int k = 0; k < KCB; k++) {
            scratch[row * 16 + k] = tv[k];
            ((int*)scratch)[row * 16 + 8 + k] = tj[k];
        }
    }
    __syncthreads();
    if (half == 0) {
#pragma unroll
        for (int k = 0; k < KCB; k++) {
            insertK<KCB>(scratch[row * 16 + k], ((int*)scratch)[row * 16 + 8 + k], tv, tj);
        }
        size_t base = ((size_t)ig * JBLK + blockIdx.y) * KCB;
#pragma unroll
        for (int k = 0; k < KCB; k++) {
            g_cand_val[base + k] = tv[k];
            g_cand_idx[base + k] = tj[k];
        }
    }
}

// merge 512 per-row candidates -> global top-32: one WARP per row
__global__ void merge_kernel() {
    int row  = blockIdx.x * (blockDim.x >> 5) + (threadIdx.x >> 5);
    int lane = threadIdx.x & 31;
    if (row >= BCUR) return;
    float lv[16]; int lj[16];
#pragma unroll
    for (int k = 0; k < 16; k++) { lv[k] = -CUDART_INF_F; lj[k] = 0x7fffffff; }
    size_t base = (size_t)row * CPR;
#pragma unroll
    for (int t = 0; t < CPR / 32; t++) {
        int c = lane + t * 32;
        insertK<16>(g_cand_val[base + c], g_cand_idx[base + c], lv, lj);
    }
    int pos = 0;
    for (int k = 0; k < KC2; k++) {
        float v = (pos < 16) ? lv[pos] : -CUDART_INF_F;
        int   j = (pos < 16) ? lj[pos] : 0x7fffffff;
        int   src = lane;
#pragma unroll
        for (int off = 16; off; off >>= 1) {
            float ov = __shfl_xor_sync(0xffffffffu, v, off);
            int   oj = __shfl_xor_sync(0xffffffffu, j, off);
            int   os = __shfl_xor_sync(0xffffffffu, src, off);
            if (better(ov, oj, v, j)) { v = ov; j = oj; src = os; }
        }
        if (lane == 0) g_cand2[row * KC2 + k] = j;
        if (lane == src) pos++;
    }
}

// fp32 rescore of 32 candidates per row (512 threads: each warp does 2);
// exact top-5 with JAX tie-break
__global__ void __launch_bounds__(512) rescore_kernel() {
    int i = blockIdx.x;
    int w = threadIdx.x >> 5;          // 0..15
    int lane = threadIdx.x & 31;
    __shared__ float sv[KC2];
    __shared__ int   sj[KC2];
    const float4* xi = (const float4*)(g_hp + (size_t)i * D);
#pragma unroll
    for (int h = 0; h < 2; h++) {
        int slot = w + h * 16;
        int j = g_cand2[i * KC2 + slot];
        const float4* xj = (const float4*)(g_hp + (size_t)j * D);
        float s = 0.f;
#pragma unroll
        for (int k = lane; k < D / 4; k += 32) {
            float4 a = xi[k], b = xj[k];
            s = fmaf(a.x, b.x, s); s = fmaf(a.y, b.y, s);
            s = fmaf(a.z, b.z, s); s = fmaf(a.w, b.w, s);
        }
#pragma unroll
        for (int off = 16; off; off >>= 1) s += __shfl_down_sync(0xffffffffu, s, off);
        if (lane == 0) { sv[slot] = s; sj[slot] = j; }
    }
    __syncthreads();
    if (threadIdx.x == 0) {
        bool used[KC2];
#pragma unroll
        for (int c = 0; c < KC2; c++) used[c] = false;
        for (int k = 0; k < KNB; k++) {
            int best = -1;
            for (int c = 0; c < KC2; c++) {
                if (used[c]) continue;
                if (best < 0 || better(sv[c], sj[c], sv[best], sj[best])) best = c;
            }
            used[best] = true;
            g_nbr[i * KNB + k] = sj[best];
        }
    }
}

// one block per row i; warp w handles neighbor w (labels are int32 on-device)
__global__ void contrib_kernel(const int* __restrict__ lprev,
                               float* __restrict__ out) {
    int i = blockIdx.x;
    int w = threadIdx.x >> 5;
    int lane = threadIdx.x & 31;
    if (w >= KNB) return;
    int j = g_nbr[i * KNB + w];
    if (j >= BCUR) return;   // only affinity[:4096,:4096] contributes
    const float4* xi = (const float4*)(g_hc + (size_t)i * D);
    const float4* xj = (const float4*)(g_hc + (size_t)j * D);
    float s = 0.f;
#pragma unroll
    for (int k = lane; k < D / 4; k += 32) {
        float4 a = xi[k], b = xj[k];
        s = fmaf(a.x, b.x, s); s = fmaf(a.y, b.y, s);
        s = fmaf(a.z, b.z, s); s = fmaf(a.w, b.w, s);
    }
#pragma unroll
    for (int off = 16; off; off >>= 1) s += __shfl_down_sync(0xffffffffu, s, off);
    if (lane == 0) {
        float d2 = fmaxf(g_sq[i] + g_sq[j] - 2.f * s, 0.f);
        float e = (lprev[i] == lprev[j]) ? 1.f : -1.f;
        const float scale = 0.5f / ((float)BCUR * (float)BCUR);  // WEIGHT / B^2
        atomicAdd(out, e * d2 * scale);
    }
}

// ---------------- launcher ----------------
extern "C" void kernel_launch(void* const* d_in, const int* in_sizes, int n_in,
                              void* d_out, int out_size) {
    const float* hidden_current  = (const float*)d_in[0];   // 4096*768
    const float* hidden_previous = (const float*)d_in[1];   // 8192*768
    const int* labels_previous   = (const int*)d_in[3];     // int32 (jax x64 off)
    float* out = (float*)d_out;

    cudaFuncSetAttribute(knn_mma_kernel,
                         cudaFuncAttributeMaxDynamicSharedMemorySize, SMEM_KNN);

    zero_out<<<1, 1>>>(out);
    normalize_all<<<BPREV + BCUR, 256>>>(hidden_previous, hidden_current);
    knn_mma_kernel<<<dim3(BCUR / 128, BPREV / 128), 256, SMEM_KNN>>>();
    merge_kernel<<<(BCUR * 32 + 255) / 256, 256>>>();
    rescore_kernel<<<BCUR, 512>>>();
    contrib_kernel<<<BCUR, KNB * 32>>>(labels_previous, out);
}

// round 12
// speedup vs baseline: 2.4502x; 2.4502x over previous
#include <cuda_runtime.h>
#include <cuda_bf16.h>
#include <math_constants.h>
#include <cstdint>

#define D      768
#define BPREV  8192
#define BCUR   4096
#define KNB    5
#define KCB    8           // candidates kept per (row, j-block)
#define KC2    16          // global candidates rescored in fp32
#define JBLK   64          // number of 128-wide j blocks (8192/128)
#define CPR    (JBLK * KCB)   // 512 candidates per row
#define KCHUNK 32          // K elements per pipeline chunk
#define NCHUNK (D / KCHUNK)   // 24
#define STAGES 4

// smem layout (bytes): A/B tiles padded to 80B per 64B row
#define SA        80
#define TILE_BYTES (128 * SA)            // 10240 (one of A or B)
#define STAGE_BYTES (2 * TILE_BYTES)     // 20480 (A then B)
#define SIM_STRIDE 132                   // floats
#define SMEM_KNN  (STAGES * STAGE_BYTES) // 81920 >= Sim (67584)

// ---------------- device scratch ----------------
__device__ float           g_hp[BPREV * D];     // normalized previous (fp32)
__device__ __nv_bfloat16   g_hp_bf[BPREV * D];  // normalized previous (bf16)
__device__ float           g_hc[BCUR * D];      // normalized current
__device__ float           g_sq[BCUR];
__device__ float g_cand_val[BCUR * CPR];
__device__ int   g_cand_idx[BCUR * CPR];
__device__ int   g_cand2[BCUR * KC2];
__device__ int   g_nbr[BCUR * KNB];

// ---------------- helpers ----------------
__device__ __forceinline__ uint32_t smem_to_u32(const void* p) {
    uint32_t a;
    asm("{ .reg .u64 t; cvta.to.shared.u64 t, %1; cvt.u32.u64 %0, t; }" : "=r"(a) : "l"(p));
    return a;
}
__device__ __forceinline__ bool better(float v1, int j1, float v2, int j2) {
    return (v1 > v2) || (v1 == v2 && j1 < j2);   // JAX top_k tie-break
}
template <int KK>
__device__ __forceinline__ void insertK(float v, int j, float* tv, int* tj) {
    if (!better(v, j, tv[KK - 1], tj[KK - 1])) return;
    tv[KK - 1] = v; tj[KK - 1] = j;
#pragma unroll
    for (int k = KK - 1; k > 0; --k) {
        if (better(tv[k], tj[k], tv[k - 1], tj[k - 1])) {
            float fv = tv[k]; tv[k] = tv[k - 1]; tv[k - 1] = fv;
            int   ij = tj[k]; tj[k] = tj[k - 1]; tj[k - 1] = ij;
        }
    }
}

// bf16 mma: D(16x8,f32) += A(16x16,bf16 row) * B(8x16,bf16 col)
__device__ __forceinline__ void mma_bf16(float* d, const uint32_t* a,
                                         const uint32_t* b, const float* c) {
    asm volatile(
        "mma.sync.aligned.m16n8k16.row.col.f32.bf16.bf16.f32 "
        "{%0,%1,%2,%3}, {%4,%5,%6,%7}, {%8,%9}, {%10,%11,%12,%13};\n"
        : "=f"(d[0]), "=f"(d[1]), "=f"(d[2]), "=f"(d[3])
        : "r"(a[0]), "r"(a[1]), "r"(a[2]), "r"(a[3]),
          "r"(b[0]), "r"(b[1]),
          "f"(c[0]), "f"(c[1]), "f"(c[2]), "f"(c[3]));
}
#define LDMATRIX_X4(r0, r1, r2, r3, addr) \
    asm volatile("ldmatrix.sync.aligned.m8n8.x4.shared.b16 {%0,%1,%2,%3}, [%4];" \
        : "=r"(r0), "=r"(r1), "=r"(r2), "=r"(r3) : "r"(addr))
#define CP_ASYNC_16(dst, src) \
    asm volatile("cp.async.cg.shared.global [%0], [%1], 16;" :: "r"(dst), "l"(src))
#define CP_ASYNC_COMMIT() asm volatile("cp.async.commit_group;")
#define CP_ASYNC_WAIT(n)  asm volatile("cp.async.wait_group %0;" :: "n"(n))

// ---------------- small kernels ----------------
__global__ void zero_out(float* out) { out[0] = 0.0f; }

// fused: blocks [0, BPREV) normalize previous -> g_hp + g_hp_bf
//        blocks [BPREV, BPREV+BCUR) normalize current -> g_hc + g_sq
__global__ void normalize_all(const float* __restrict__ prev,
                              const float* __restrict__ cur) {
    const bool is_prev = blockIdx.x < BPREV;
    const int r = is_prev ? blockIdx.x : blockIdx.x - BPREV;
    const float* x = (is_prev ? prev : cur) + (size_t)r * D;
    __shared__ float red[256];
    float s = 0.f;
    for (int k = threadIdx.x; k < D; k += 256) { float v = x[k]; s += v * v; }
    red[threadIdx.x] = s;
    __syncthreads();
    for (int off = 128; off > 0; off >>= 1) {
        if (threadIdx.x < off) red[threadIdx.x] += red[threadIdx.x + off];
        __syncthreads();
    }
    float denom = fmaxf(sqrtf(red[0]), 1e-12f);
    float s2 = 0.f;
    for (int k = threadIdx.x; k < D; k += 256) {
        float v = x[k] / denom;
        if (is_prev) {
            g_hp[(size_t)r * D + k] = v;
            g_hp_bf[(size_t)r * D + k] = __float2bfloat16(v);
        } else {
            g_hc[(size_t)r * D + k] = v;
            s2 += v * v;
        }
    }
    if (!is_prev) {
        __syncthreads();
        red[threadIdx.x] = s2;
        __syncthreads();
        for (int off = 128; off > 0; off >>= 1) {
            if (threadIdx.x < off) red[threadIdx.x] += red[threadIdx.x + off];
            __syncthreads();
        }
        if (threadIdx.x == 0) g_sq[r] = red[0];
    }
}

// ---------------- tensor-core kNN (bf16 mma.sync + ldmatrix + cp.async) ------
// grid (32, 64): 128 i-rows x 128 j-cols per CTA. 8 warps as 2(M) x 4(N).
__global__ void __launch_bounds__(256) knn_mma_kernel() {
    extern __shared__ char smem[];
    uint32_t smem_u32 = smem_to_u32(smem);
    const int tid    = threadIdx.x;
    const int wid    = tid >> 5;
    const int lane   = tid & 31;
    const int warp_m = wid >> 2;       // 0..1 -> rows warp_m*64
    const int warp_n = wid & 3;        // 0..3 -> cols warp_n*32
    const int i0 = blockIdx.x * 128;
    const int j0 = blockIdx.y * 128;

    float acc[4][4][4];
#pragma unroll
    for (int mf = 0; mf < 4; mf++)
#pragma unroll
        for (int nf = 0; nf < 4; nf++)
#pragma unroll
            for (int r = 0; r < 4; r++) acc[mf][nf][r] = 0.f;

    // staging: each thread copies 2x16B of A and 2x16B of B per chunk
    const int ld_row = tid >> 2;        // 0..63 (+64 for q=1)
    const int ld_c16 = tid & 3;
    const char* srcA0 = (const char*)&g_hp_bf[(size_t)(i0 + ld_row) * D + ld_c16 * 8];
    const char* srcA1 = (const char*)&g_hp_bf[(size_t)(i0 + 64 + ld_row) * D + ld_c16 * 8];
    const char* srcB0 = (const char*)&g_hp_bf[(size_t)(j0 + ld_row) * D + ld_c16 * 8];
    const char* srcB1 = (const char*)&g_hp_bf[(size_t)(j0 + 64 + ld_row) * D + ld_c16 * 8];
    const uint32_t dstA0 = smem_u32 + ld_row * SA + ld_c16 * 16;
    const uint32_t dstA1 = smem_u32 + (64 + ld_row) * SA + ld_c16 * 16;
    const uint32_t dstB0 = dstA0 + TILE_BYTES;
    const uint32_t dstB1 = dstA1 + TILE_BYTES;

    // ldmatrix lane-address components (constant across chunks)
    const int a_row_in  = (lane & 15);
    const int a_colbyte = (lane >> 4) * 16;
    const int b_row_in  = (lane & 7) + ((lane >> 4) << 3);
    const int b_colbyte = ((lane >> 3) & 1) * 16;
    const uint32_t aAddrBase = smem_u32 +
        (uint32_t)((warp_m * 64 + a_row_in) * SA + a_colbyte);
    const uint32_t bAddrBase = smem_u32 + TILE_BYTES +
        (uint32_t)((warp_n * 32 + b_row_in) * SA + b_colbyte);

    // prologue: issue first STAGES-1 chunks
#pragma unroll
    for (int s = 0; s < STAGES - 1; s++) {
        const uint32_t so = s * STAGE_BYTES;
        const size_t go = (size_t)s * KCHUNK * 2;   // bytes
        CP_ASYNC_16(dstA0 + so, srcA0 + go);
        CP_ASYNC_16(dstA1 + so, srcA1 + go);
        CP_ASYNC_16(dstB0 + so, srcB0 + go);
        CP_ASYNC_16(dstB1 + so, srcB1 + go);
        CP_ASYNC_COMMIT();
    }

    for (int c = 0; c < NCHUNK; c++) {
        CP_ASYNC_WAIT(STAGES - 2);
        __syncthreads();

        const uint32_t so = (uint32_t)(c & (STAGES - 1)) * STAGE_BYTES;
        uint32_t a[4][2][4];
        uint32_t b[2][4][2];
#pragma unroll
        for (int ks = 0; ks < 2; ks++) {
#pragma unroll
            for (int mf = 0; mf < 4; mf++) {
                uint32_t addr = aAddrBase + so + (uint32_t)(mf * 16 * SA + ks * 32);
                LDMATRIX_X4(a[mf][ks][0], a[mf][ks][1], a[mf][ks][2], a[mf][ks][3], addr);
            }
#pragma unroll
            for (int nf2 = 0; nf2 < 2; nf2++) {
                uint32_t addr = bAddrBase + so + (uint32_t)(nf2 * 16 * SA + ks * 32);
                LDMATRIX_X4(b[ks][nf2 * 2][0], b[ks][nf2 * 2][1],
                            b[ks][nf2 * 2 + 1][0], b[ks][nf2 * 2 + 1][1], addr);
            }
        }
#pragma unroll
        for (int ks = 0; ks < 2; ks++)
#pragma unroll
            for (int mf = 0; mf < 4; mf++)
#pragma unroll
                for (int nf = 0; nf < 4; nf++)
                    mma_bf16(acc[mf][nf], a[mf][ks], b[ks][nf], acc[mf][nf]);

        // issue chunk c+STAGES-1 into the stage just freed
        const int cn = c + STAGES - 1;
        if (cn < NCHUNK) {
            const uint32_t sn = (uint32_t)(cn & (STAGES - 1)) * STAGE_BYTES;
            const size_t gn = (size_t)cn * KCHUNK * 2;
            CP_ASYNC_16(dstA0 + sn, srcA0 + gn);
            CP_ASYNC_16(dstA1 + sn, srcA1 + gn);
            CP_ASYNC_16(dstB0 + sn, srcB0 + gn);
            CP_ASYNC_16(dstB1 + sn, srcB1 + gn);
        }
        CP_ASYNC_COMMIT();
    }
    CP_ASYNC_WAIT(0);
    __syncthreads();

    // stage sims to smem (reuses GEMM buffer space; mainloop fully drained)
    float* Sim = (float*)smem;
#pragma unroll
    for (int mf = 0; mf < 4; mf++) {
        int r0 = warp_m * 64 + mf * 16 + (lane >> 2);
#pragma unroll
        for (int nf = 0; nf < 4; nf++) {
            int c0 = warp_n * 32 + nf * 8 + (lane & 3) * 2;
            Sim[r0 * SIM_STRIDE + c0]           = acc[mf][nf][0];
            Sim[r0 * SIM_STRIDE + c0 + 1]       = acc[mf][nf][1];
            Sim[(r0 + 8) * SIM_STRIDE + c0]     = acc[mf][nf][2];
            Sim[(r0 + 8) * SIM_STRIDE + c0 + 1] = acc[mf][nf][3];
        }
    }
    __syncthreads();

    // scan: 2 threads per row, 64 cols each, keep top-8 per half
    const int row  = tid >> 1;
    const int half = tid & 1;
    const int ig   = i0 + row;
    float tv[KCB]; int tj[KCB];
#pragma unroll
    for (int k = 0; k < KCB; k++) { tv[k] = -CUDART_INF_F; tj[k] = 0x7fffffff; }
#pragma unroll 4
    for (int c0 = 0; c0 < 64; c0++) {
        int cc = half * 64 + c0;
        float v = Sim[row * SIM_STRIDE + cc];
        int jg = j0 + cc;
        if (jg != ig) insertK<KCB>(v, jg, tv, tj);
    }
    __syncthreads();
    // half 1 parks its list in smem scratch (Sim area is free now)
    float* scratch = (float*)smem;          // 128 rows x 16 slots
    if (half == 1) {
#pragma unroll
        for (int k = 0; k < KCB; k++) {
            scratch[row * 16 + k] = tv[k];
            ((int*)scratch)[row * 16 + 8 + k] = tj[k];
        }
    }
    __syncthreads();
    if (half == 0) {
#pragma unroll
        for (int k = 0; k < KCB; k++) {
            insertK<KCB>(scratch[row * 16 + k], ((int*)scratch)[row * 16 + 8 + k], tv, tj);
        }
        size_t base = ((size_t)ig * JBLK + blockIdx.y) * KCB;
#pragma unroll
        for (int k = 0; k < KCB; k++) {
            g_cand_val[base + k] = tv[k];
            g_cand_idx[base + k] = tj[k];
        }
    }
}

// merge 512 per-row candidates -> global top-16: one WARP per row.
// Each lane bulk-loads its contiguous 16 candidates (4xfloat4 + 4xint4),
// filters to lane-local top-8 in registers, then 16 warp-argmax pops.
__global__ void merge_kernel() {
    int row  = blockIdx.x * (blockDim.x >> 5) + (threadIdx.x >> 5);
    int lane = threadIdx.x & 31;
    if (row >= BCUR) return;

    size_t base = (size_t)row * CPR + (size_t)lane * 16;
    float vbuf[16]; int jbuf[16];
#pragma unroll
    for (int q = 0; q < 4; q++) {
        float4 v4 = *(const float4*)&g_cand_val[base + q * 4];
        int4   j4 = *(const int4*)&g_cand_idx[base + q * 4];
        vbuf[q * 4 + 0] = v4.x; vbuf[q * 4 + 1] = v4.y;
        vbuf[q * 4 + 2] = v4.z; vbuf[q * 4 + 3] = v4.w;
        jbuf[q * 4 + 0] = j4.x; jbuf[q * 4 + 1] = j4.y;
        jbuf[q * 4 + 2] = j4.z; jbuf[q * 4 + 3] = j4.w;
    }
    float lv[8]; int lj[8];
#pragma unroll
    for (int k = 0; k < 8; k++) { lv[k] = -CUDART_INF_F; lj[k] = 0x7fffffff; }
#pragma unroll
    for (int t = 0; t < 16; t++) insertK<8>(vbuf[t], jbuf[t], lv, lj);

    int pos = 0;
    for (int k = 0; k < KC2; k++) {
        float v = (pos < 8) ? lv[pos] : -CUDART_INF_F;
        int   j = (pos < 8) ? lj[pos] : 0x7fffffff;
        int   src = lane;
#pragma unroll
        for (int off = 16; off; off >>= 1) {
            float ov = __shfl_xor_sync(0xffffffffu, v, off);
            int   oj = __shfl_xor_sync(0xffffffffu, j, off);
            int   os = __shfl_xor_sync(0xffffffffu, src, off);
            if (better(ov, oj, v, j)) { v = ov; j = oj; src = os; }
        }
        if (lane == 0) g_cand2[row * KC2 + k] = j;
        if (lane == src) pos++;
    }
}

// fp32 rescore of 16 candidates per row; exact top-5 with JAX tie-break
__global__ void __launch_bounds__(512) rescore_kernel() {
    int i = blockIdx.x;
    int w = threadIdx.x >> 5;
    int lane = threadIdx.x & 31;
    __shared__ float sv[KC2];
    __shared__ int   sj[KC2];
    int j = g_cand2[i * KC2 + w];
    const float4* xi = (const float4*)(g_hp + (size_t)i * D);
    const float4* xj = (const float4*)(g_hp + (size_t)j * D);
    float s = 0.f;
#pragma unroll
    for (int k = lane; k < D / 4; k += 32) {
        float4 a = xi[k], b = xj[k];
        s = fmaf(a.x, b.x, s); s = fmaf(a.y, b.y, s);
        s = fmaf(a.z, b.z, s); s = fmaf(a.w, b.w, s);
    }
#pragma unroll
    for (int off = 16; off; off >>= 1) s += __shfl_down_sync(0xffffffffu, s, off);
    if (lane == 0) { sv[w] = s; sj[w] = j; }
    __syncthreads();
    if (threadIdx.x == 0) {
        bool used[KC2];
#pragma unroll
        for (int c = 0; c < KC2; c++) used[c] = false;
        for (int k = 0; k < KNB; k++) {
            int best = -1;
            for (int c = 0; c < KC2; c++) {
                if (used[c]) continue;
                if (best < 0 || better(sv[c], sj[c], sv[best], sj[best])) best = c;
            }
            used[best] = true;
            g_nbr[i * KNB + k] = sj[best];
        }
    }
}

// one block per row i; warp w handles neighbor w (labels are int32 on-device)
__global__ void contrib_kernel(const int* __restrict__ lprev,
                               float* __restrict__ out) {
    int i = blockIdx.x;
    int w = threadIdx.x >> 5;
    int lane = threadIdx.x & 31;
    if (w >= KNB) return;
    int j = g_nbr[i * KNB + w];
    if (j >= BCUR) return;   // only affinity[:4096,:4096] contributes
    const float4* xi = (const float4*)(g_hc + (size_t)i * D);
    const float4* xj = (const float4*)(g_hc + (size_t)j * D);
    float s = 0.f;
#pragma unroll
    for (int k = lane; k < D / 4; k += 32) {
        float4 a = xi[k], b = xj[k];
        s = fmaf(a.x, b.x, s); s = fmaf(a.y, b.y, s);
        s = fmaf(a.z, b.z, s); s = fmaf(a.w, b.w, s);
    }
#pragma unroll
    for (int off = 16; off; off >>= 1) s += __shfl_down_sync(0xffffffffu, s, off);
    if (lane == 0) {
        float d2 = fmaxf(g_sq[i] + g_sq[j] - 2.f * s, 0.f);
        float e = (lprev[i] == lprev[j]) ? 1.f : -1.f;
        const float scale = 0.5f / ((float)BCUR * (float)BCUR);  // WEIGHT / B^2
        atomicAdd(out, e * d2 * scale);
    }
}

// ---------------- launcher ----------------
extern "C" void kernel_launch(void* const* d_in, const int* in_sizes, int n_in,
                              void* d_out, int out_size) {
    const float* hidden_current  = (const float*)d_in[0];   // 4096*768
    const float* hidden_previous = (const float*)d_in[1];   // 8192*768
    const int* labels_previous   = (const int*)d_in[3];     // int32 (jax x64 off)
    float* out = (float*)d_out;

    cudaFuncSetAttribute(knn_mma_kernel,
                         cudaFuncAttributeMaxDynamicSharedMemorySize, SMEM_KNN);

    zero_out<<<1, 1>>>(out);
    normalize_all<<<BPREV + BCUR, 256>>>(hidden_previous, hidden_current);
    knn_mma_kernel<<<dim3(BCUR / 128, BPREV / 128), 256, SMEM_KNN>>>();
    merge_kernel<<<(BCUR * 32 + 255) / 256, 256>>>();
    rescore_kernel<<<BCUR, KC2 * 32>>>();
    contrib_kernel<<<BCUR, KNB * 32>>>(labels_previous, out);
}